// round 6
// baseline (speedup 1.0000x reference)
#include <cuda_runtime.h>
#include <cuda_bf16.h>
#include <cstdint>

// ---------------- problem constants ----------------
#define M_ROWS   4096
#define K_DIM    784
#define K_PAD    800           // 784 padded to 25*32
#define N_BASAL  16384
#define NUM_CLS  10
#define NUM_ACT  492
#define DELTA    0.03f         // margin for bf16 GEMM error
#define MAXC     384           // candidate buffer per row

// ---------------- GEMM tiling ----------------
#define BM 128
#define BN 128
#define BK 32
#define NCHUNK (K_PAD / BK)    // 25
#define NSTAGE 4
#define ROW_BYTES 80           // 64B data + 16B skew (bank-conflict-free)
#define A_STAGE_BYTES (BM * ROW_BYTES)
#define B_STAGE_BYTES (BN * ROW_BYTES)
#define STAGE_BYTES (A_STAGE_BYTES + B_STAGE_BYTES)
#define SMEM_TOTAL (NSTAGE * STAGE_BYTES)   // 81920

// ---------------- scratch (device globals; no allocs allowed) ----------------
__device__ float          g_act[(size_t)M_ROWS * N_BASAL];   // 256 MB approx activations
__device__ unsigned int   g_mask[N_BASAL];
__device__ __nv_bfloat16  g_A[(size_t)M_ROWS * K_PAD];       // bf16 image, padded
__device__ __nv_bfloat16  g_B[(size_t)N_BASAL * K_PAD];      // bf16 proj^T, padded
__device__ float          g_Bt[(size_t)N_BASAL * K_DIM];     // fp32 proj^T (rescore)

// ---------------- asm helpers ----------------
__device__ __forceinline__ uint32_t smem_u32(const void* p) {
    uint32_t a;
    asm("{ .reg .u64 t; cvta.to.shared.u64 t, %1; cvt.u32.u64 %0, t; }" : "=r"(a) : "l"(p));
    return a;
}
__device__ __forceinline__ void cp_async16(uint32_t dst, const void* src) {
    asm volatile("cp.async.cg.shared.global [%0], [%1], 16;" :: "r"(dst), "l"(src) : "memory");
}
__device__ __forceinline__ void cp_commit() {
    asm volatile("cp.async.commit_group;" ::: "memory");
}
template <int N>
__device__ __forceinline__ void cp_wait() {
    asm volatile("cp.async.wait_group %0;" :: "n"(N) : "memory");
}
__device__ __forceinline__ void ldm_x4(uint32_t* r, uint32_t addr) {
    asm volatile("ldmatrix.sync.aligned.m8n8.x4.shared.b16 {%0,%1,%2,%3}, [%4];"
                 : "=r"(r[0]), "=r"(r[1]), "=r"(r[2]), "=r"(r[3]) : "r"(addr));
}
__device__ __forceinline__ void mma_bf16(float* c, const uint32_t* a, uint32_t b0, uint32_t b1) {
    asm volatile("mma.sync.aligned.m16n8k16.row.col.f32.bf16.bf16.f32 "
                 "{%0,%1,%2,%3}, {%4,%5,%6,%7}, {%8,%9}, {%0,%1,%2,%3};"
                 : "+f"(c[0]), "+f"(c[1]), "+f"(c[2]), "+f"(c[3])
                 : "r"(a[0]), "r"(a[1]), "r"(a[2]), "r"(a[3]), "r"(b0), "r"(b1));
}

// ---------------------------------------------------------------------------
// pack synapses into bitmasks
// ---------------------------------------------------------------------------
__global__ void pack_syn_kernel(const float* __restrict__ syn) {
    int j = blockIdx.x * blockDim.x + threadIdx.x;
    if (j < N_BASAL) {
        unsigned int m = 0;
#pragma unroll
        for (int c = 0; c < NUM_CLS; ++c)
            m |= (syn[c * N_BASAL + j] > 0.5f) ? (1u << c) : 0u;
        g_mask[j] = m;
    }
}

// ---------------------------------------------------------------------------
// A: bf16(image), K padded with zeros
// ---------------------------------------------------------------------------
__global__ void conv_a_kernel(const float* __restrict__ img) {
    size_t idx = (size_t)blockIdx.x * 256 + threadIdx.x;   // 4096*800
    int m = (int)(idx / K_PAD);
    int k = (int)(idx % K_PAD);
    g_A[idx] = (k < K_DIM) ? __float2bfloat16(img[(size_t)m * K_DIM + k])
                           : __float2bfloat16(0.0f);
}

// ---------------------------------------------------------------------------
// B: transpose proj -> bf16 g_B [n][K_PAD] and fp32 g_Bt [n][K_DIM]
// ---------------------------------------------------------------------------
__global__ void conv_b_kernel(const float* __restrict__ proj) {
    __shared__ float t[32][33];
    int k0 = blockIdx.x * 32, n0 = blockIdx.y * 32;
    int tx = threadIdx.x, ty = threadIdx.y;   // 32 x 8
#pragma unroll
    for (int i = 0; i < 32; i += 8) {
        int kk = k0 + ty + i;
        t[ty + i][tx] = (kk < K_DIM) ? proj[(size_t)kk * N_BASAL + n0 + tx] : 0.0f;
    }
    __syncthreads();
#pragma unroll
    for (int i = 0; i < 32; i += 8) {
        int n = n0 + ty + i;
        int k = k0 + tx;
        if (k < K_PAD) {
            float v = t[tx][ty + i];
            g_B[(size_t)n * K_PAD + k] = __float2bfloat16(v);
            if (k < K_DIM) g_Bt[(size_t)n * K_DIM + k] = v;
        }
    }
}

// ---------------------------------------------------------------------------
// mma.sync bf16 GEMM: g_act[M,N] = g_A[M,Kp] * g_B[N,Kp]^T  (fp32 accum)
//   4-stage pipeline, prefetch distance 3, ONE barrier per K-chunk,
//   tail uses empty commit groups so wait_group<2> always excludes chunk c.
// ---------------------------------------------------------------------------
__global__ __launch_bounds__(256, 2)
void gemm_mma_kernel() {
    extern __shared__ char smem[];
    const uint32_t sb = smem_u32(smem);
    const int tid = threadIdx.x;
    const int lane = tid & 31;
    const int wid = tid >> 5;
    const int warpM = wid >> 2;
    const int warpN = wid & 3;
    const int m0 = blockIdx.y * BM;
    const int n0 = blockIdx.x * BN;

    const char* Abase = (const char*)g_A + (size_t)m0 * (K_PAD * 2);
    const char* Bbase = (const char*)g_B + (size_t)n0 * (K_PAD * 2);

    const int ar = tid >> 2;
    const int ac = tid & 3;

    auto load_stage = [&](int c, int s) {
        const uint32_t st = sb + s * STAGE_BYTES;
        const size_t koff = (size_t)c * (BK * 2);
        cp_async16(st + ar * ROW_BYTES + ac * 16,
                   Abase + (size_t)ar * (K_PAD * 2) + koff + ac * 16);
        cp_async16(st + (ar + 64) * ROW_BYTES + ac * 16,
                   Abase + (size_t)(ar + 64) * (K_PAD * 2) + koff + ac * 16);
        const uint32_t stB = st + A_STAGE_BYTES;
        cp_async16(stB + ar * ROW_BYTES + ac * 16,
                   Bbase + (size_t)ar * (K_PAD * 2) + koff + ac * 16);
        cp_async16(stB + (ar + 64) * ROW_BYTES + ac * 16,
                   Bbase + (size_t)(ar + 64) * (K_PAD * 2) + koff + ac * 16);
        cp_commit();
    };

    float acc[4][4][4];
#pragma unroll
    for (int i = 0; i < 4; ++i)
#pragma unroll
        for (int j = 0; j < 4; ++j)
#pragma unroll
            for (int q = 0; q < 4; ++q) acc[i][j][q] = 0.0f;

    const int lrow = lane & 15;
    const int lcol16 = (lane >> 4) << 4;

    load_stage(0, 0);
    load_stage(1, 1);
    load_stage(2, 2);

    for (int c = 0; c < NCHUNK; ++c) {
        const int s = c & 3;
        cp_wait<2>();
        __syncthreads();
        if (c + 3 < NCHUNK) load_stage(c + 3, (c + 3) & 3);
        else cp_commit();   // empty group: keeps wait_group accounting safe

        const uint32_t stA = sb + s * STAGE_BYTES;
        const uint32_t stB = stA + A_STAGE_BYTES;
#pragma unroll
        for (int ks = 0; ks < 2; ++ks) {
            const int kbyte = ks * 32 + lcol16;
            uint32_t af[4][4];
#pragma unroll
            for (int mt = 0; mt < 4; ++mt)
                ldm_x4(af[mt], stA + (warpM * 64 + mt * 16 + lrow) * ROW_BYTES + kbyte);
            uint32_t bf[2][4];
#pragma unroll
            for (int nt = 0; nt < 2; ++nt)
                ldm_x4(bf[nt], stB + (warpN * 32 + nt * 16 + lrow) * ROW_BYTES + kbyte);
#pragma unroll
            for (int mt = 0; mt < 4; ++mt) {
#pragma unroll
                for (int n8 = 0; n8 < 4; ++n8) {
                    const int nt = n8 >> 1, hi = n8 & 1;
                    mma_bf16(acc[mt][n8], af[mt], bf[nt][hi], bf[nt][hi + 2]);
                }
            }
        }
        // no trailing barrier: next iteration's top barrier orders reuse
    }

    const int grp = lane >> 2;
    const int tj  = lane & 3;
#pragma unroll
    for (int mt = 0; mt < 4; ++mt) {
#pragma unroll
        for (int n8 = 0; n8 < 4; ++n8) {
            const int row = m0 + warpM * 64 + mt * 16 + grp;
            const int col = n0 + warpN * 32 + n8 * 8 + tj * 2;
            float* p0 = g_act + (size_t)row * N_BASAL + col;
            float* p1 = g_act + (size_t)(row + 8) * N_BASAL + col;
            *(float2*)p0 = make_float2(acc[mt][n8][0], acc[mt][n8][1]);
            *(float2*)p1 = make_float2(acc[mt][n8][2], acc[mt][n8][3]);
        }
    }
}

// ---------------------------------------------------------------------------
// select + overlap: 2 radix passes (22-bit threshold) + margin classify +
// exact fp32 rescore of candidates + exact rank. One block / row.
// ---------------------------------------------------------------------------
__device__ __forceinline__ unsigned int f2key(float f) {
    unsigned int u = __float_as_uint(f);
    return (u & 0x80000000u) ? ~u : (u | 0x80000000u);
}
__device__ __forceinline__ float key2f(unsigned int k) {
    unsigned int u = (k & 0x80000000u) ? (k & 0x7FFFFFFFu) : ~k;
    return __uint_as_float(u);
}

__global__ __launch_bounds__(256)
void select_overlap_kernel(const float* __restrict__ img, float* __restrict__ out) {
    const int row = blockIdx.x;
    const float* a = g_act + (size_t)row * N_BASAL;
    const float4* a4 = (const float4*)a;
    const int tid = threadIdx.x;
    const int lane = tid & 31;
    const int wid = tid >> 5;

    __shared__ unsigned int hist[2048];
    __shared__ float4 s_img[K_DIM / 4];   // 196 float4
    __shared__ unsigned int s_kk, s_prefix;
    __shared__ int ov[NUM_CLS];
    __shared__ int s_ncand, s_nsure;
    __shared__ int   cand_idx[MAXC];
    __shared__ float cand_val[MAXC];

    // cache image row (for rescore)
    const float4* img4 = (const float4*)(img + (size_t)row * K_DIM);
    for (int k = tid; k < K_DIM / 4; k += 256) s_img[k] = img4[k];

    if (tid == 0) { s_kk = NUM_ACT; s_prefix = 0; s_ncand = 0; s_nsure = 0; }
    if (tid < NUM_CLS) ov[tid] = 0;
    for (int i = tid; i < 2048; i += 256) hist[i] = 0;
    __syncthreads();

    // ---- pass 0: hist on top 11 bits of ordered key ----
    for (int j = tid; j < N_BASAL / 4; j += 256) {
        float4 v = a4[j];
        atomicAdd(&hist[f2key(v.x) >> 21], 1u);
        atomicAdd(&hist[f2key(v.y) >> 21], 1u);
        atomicAdd(&hist[f2key(v.z) >> 21], 1u);
        atomicAdd(&hist[f2key(v.w) >> 21], 1u);
    }
    __syncthreads();

    // ---- warp-0 descending scan helper (inline twice) ----
#define SCAN_PASS(PASS)                                                          \
    if (wid == 0) {                                                              \
        const unsigned int kk = s_kk;                                            \
        unsigned int sum = 0;                                                    \
        for (int i = 0; i < 64; ++i) sum += hist[2047 - lane * 64 - i];          \
        unsigned int pre = sum;                                                  \
        for (int o = 1; o < 32; o <<= 1) {                                       \
            unsigned int t = __shfl_up_sync(0xFFFFFFFFu, pre, o);                \
            if (lane >= o) pre += t;                                             \
        }                                                                        \
        const unsigned int excl = pre - sum;                                     \
        if (excl < kk && excl + sum >= kk) {                                     \
            unsigned int before = excl;                                          \
            int sel = 0;                                                         \
            for (int i = 0; i < 64; ++i) {                                       \
                int b = 2047 - lane * 64 - i;                                    \
                unsigned int cc = hist[b];                                       \
                if (before + cc >= kk) { sel = b; break; }                       \
                before += cc;                                                    \
            }                                                                    \
            s_kk = kk - before;                                                  \
            s_prefix = (PASS == 0) ? (unsigned int)sel                           \
                                   : ((s_prefix << 11) | (unsigned int)sel);     \
        }                                                                        \
    }

    SCAN_PASS(0);
    __syncthreads();
    const unsigned int prefix0 = s_prefix;
    for (int i = tid; i < 2048; i += 256) hist[i] = 0;
    __syncthreads();

    // ---- pass 1: hist on bits [20:10] within selected top bin ----
    for (int j = tid; j < N_BASAL / 4; j += 256) {
        float4 v = a4[j];
        unsigned int k0 = f2key(v.x), k1 = f2key(v.y), k2 = f2key(v.z), k3 = f2key(v.w);
        if ((k0 >> 21) == prefix0) atomicAdd(&hist[(k0 >> 10) & 2047u], 1u);
        if ((k1 >> 21) == prefix0) atomicAdd(&hist[(k1 >> 10) & 2047u], 1u);
        if ((k2 >> 21) == prefix0) atomicAdd(&hist[(k2 >> 10) & 2047u], 1u);
        if ((k3 >> 21) == prefix0) atomicAdd(&hist[(k3 >> 10) & 2047u], 1u);
    }
    __syncthreads();
    SCAN_PASS(1);
    __syncthreads();
#undef SCAN_PASS

    // 22-bit threshold; remaining 10 key bits unknown (< ~5e-4) << margin
    const float tauf  = key2f(s_prefix << 10);
    const float hicut = tauf + 2.0f * DELTA;
    const float locut = tauf - 2.0f * DELTA;

    // ---- classify pass ----
    int cnt[NUM_CLS];
#pragma unroll
    for (int c = 0; c < NUM_CLS; ++c) cnt[c] = 0;
    int nsure = 0;

    for (int j = tid; j < N_BASAL / 4; j += 256) {
        float4 v = a4[j];
        const float vv[4] = {v.x, v.y, v.z, v.w};
#pragma unroll
        for (int q = 0; q < 4; ++q) {
            float x = vv[q];
            if (x > hicut) {
                unsigned int m = g_mask[j * 4 + q];
#pragma unroll
                for (int c = 0; c < NUM_CLS; ++c) cnt[c] += (m >> c) & 1u;
                ++nsure;
            } else if (x >= locut) {
                int p = atomicAdd(&s_ncand, 1);
                if (p < MAXC) cand_idx[p] = j * 4 + q;
            }
        }
    }
    atomicAdd(&s_nsure, nsure);
    __syncthreads();

    const int C = (s_ncand < MAXC) ? s_ncand : MAXC;
    const int k_remain = NUM_ACT - s_nsure;

    // ---- exact fp32 rescore: one warp per candidate ----
    for (int c = wid; c < C; c += 8) {
        const float4* brow = (const float4*)(g_Bt + (size_t)cand_idx[c] * K_DIM);
        float s = 0.0f;
        for (int k = lane; k < K_DIM / 4; k += 32) {
            float4 b = brow[k];
            float4 im = s_img[k];
            s = fmaf(im.x, b.x, s);
            s = fmaf(im.y, b.y, s);
            s = fmaf(im.z, b.z, s);
            s = fmaf(im.w, b.w, s);
        }
#pragma unroll
        for (int o = 16; o > 0; o >>= 1)
            s += __shfl_xor_sync(0xFFFFFFFFu, s, o);
        if (lane == 0) cand_val[c] = s;
    }
    __syncthreads();

    // ---- exact rank among candidates (value desc, index asc) ----
    for (int c = tid; c < C; c += 256) {
        const float vc = cand_val[c];
        const int ic = cand_idx[c];
        int rank = 0;
        for (int d = 0; d < C; ++d) {
            float vd = cand_val[d];
            rank += (vd > vc || (vd == vc && cand_idx[d] < ic)) ? 1 : 0;
        }
        if (rank < k_remain) {
            unsigned int m = g_mask[ic];
#pragma unroll
            for (int cc = 0; cc < NUM_CLS; ++cc) cnt[cc] += (m >> cc) & 1u;
        }
    }

#pragma unroll
    for (int c = 0; c < NUM_CLS; ++c)
        if (cnt[c]) atomicAdd(&ov[c], cnt[c]);
    __syncthreads();

    if (tid < NUM_CLS)
        out[row * NUM_CLS + tid] = (float)ov[tid];
}

// ---------------------------------------------------------------------------
// Launch
// ---------------------------------------------------------------------------
extern "C" void kernel_launch(void* const* d_in, const int* in_sizes, int n_in,
                              void* d_out, int out_size) {
    const float* image = (const float*)d_in[0];   // [4096, 784]
    const float* proj  = (const float*)d_in[1];   // [784, 16384]
    const float* syn   = (const float*)d_in[2];   // [10, 16384]
    float* out = (float*)d_out;                   // [4096, 10]

    cudaFuncSetAttribute(gemm_mma_kernel, cudaFuncAttributeMaxDynamicSharedMemorySize, SMEM_TOTAL);

    pack_syn_kernel<<<(N_BASAL + 255) / 256, 256>>>(syn);
    conv_a_kernel<<<(int)(((size_t)M_ROWS * K_PAD) / 256), 256>>>(image);
    {
        dim3 grid(K_PAD / 32, N_BASAL / 32);      // 25 x 512
        conv_b_kernel<<<grid, dim3(32, 8)>>>(proj);
    }
    {
        dim3 grid(N_BASAL / BN, M_ROWS / BM);     // 128 x 32
        gemm_mma_kernel<<<grid, 256, SMEM_TOTAL>>>();
    }
    select_overlap_kernel<<<M_ROWS, 256>>>(image, out);
}

// round 7
// speedup vs baseline: 1.1228x; 1.1228x over previous
#include <cuda_runtime.h>
#include <cuda_bf16.h>
#include <cuda_fp16.h>
#include <cstdint>

// ---------------- problem constants ----------------
#define M_ROWS   4096
#define K_DIM    784
#define K_PAD    800           // 784 padded to 25*32
#define N_BASAL  16384
#define NUM_CLS  10
#define NUM_ACT  492
#define DELTA    0.03f         // covers bf16 GEMM err + fp16 storage err
#define MAXC     384           // candidate buffer per row

// histogram: 2048 bins over [-16, 16), width 1/64
#define HBINS    2048
#define HLO      (-16.0f)
#define HSCALE   64.0f
#define HWIDTH   (1.0f / 64.0f)

// ---------------- GEMM tiling ----------------
#define BM 128
#define BN 128
#define BK 32
#define NCHUNK (K_PAD / BK)    // 25
#define NSTAGE 4
#define ROW_BYTES 80
#define A_STAGE_BYTES (BM * ROW_BYTES)
#define B_STAGE_BYTES (BN * ROW_BYTES)
#define STAGE_BYTES (A_STAGE_BYTES + B_STAGE_BYTES)
#define SMEM_TOTAL (NSTAGE * STAGE_BYTES)   // 81920

// ---------------- scratch (device globals; no allocs allowed) ----------------
__device__ __half         g_act[(size_t)M_ROWS * N_BASAL];   // 128 MB approx activations
__device__ unsigned int   g_mask[N_BASAL];
__device__ __nv_bfloat16  g_A[(size_t)M_ROWS * K_PAD];       // bf16 image, padded
__device__ __nv_bfloat16  g_B[(size_t)N_BASAL * K_PAD];      // bf16 proj^T, padded
__device__ float          g_Bt[(size_t)N_BASAL * K_DIM];     // fp32 proj^T (rescore)

// ---------------- asm helpers ----------------
__device__ __forceinline__ uint32_t smem_u32(const void* p) {
    uint32_t a;
    asm("{ .reg .u64 t; cvta.to.shared.u64 t, %1; cvt.u32.u64 %0, t; }" : "=r"(a) : "l"(p));
    return a;
}
__device__ __forceinline__ void cp_async16(uint32_t dst, const void* src) {
    asm volatile("cp.async.cg.shared.global [%0], [%1], 16;" :: "r"(dst), "l"(src) : "memory");
}
__device__ __forceinline__ void cp_commit() {
    asm volatile("cp.async.commit_group;" ::: "memory");
}
template <int N>
__device__ __forceinline__ void cp_wait() {
    asm volatile("cp.async.wait_group %0;" :: "n"(N) : "memory");
}
__device__ __forceinline__ void ldm_x4(uint32_t* r, uint32_t addr) {
    asm volatile("ldmatrix.sync.aligned.m8n8.x4.shared.b16 {%0,%1,%2,%3}, [%4];"
                 : "=r"(r[0]), "=r"(r[1]), "=r"(r[2]), "=r"(r[3]) : "r"(addr));
}
__device__ __forceinline__ void mma_bf16(float* c, const uint32_t* a, uint32_t b0, uint32_t b1) {
    asm volatile("mma.sync.aligned.m16n8k16.row.col.f32.bf16.bf16.f32 "
                 "{%0,%1,%2,%3}, {%4,%5,%6,%7}, {%8,%9}, {%0,%1,%2,%3};"
                 : "+f"(c[0]), "+f"(c[1]), "+f"(c[2]), "+f"(c[3])
                 : "r"(a[0]), "r"(a[1]), "r"(a[2]), "r"(a[3]), "r"(b0), "r"(b1));
}

// ---------------------------------------------------------------------------
// pack synapses into bitmasks
// ---------------------------------------------------------------------------
__global__ void pack_syn_kernel(const float* __restrict__ syn) {
    int j = blockIdx.x * blockDim.x + threadIdx.x;
    if (j < N_BASAL) {
        unsigned int m = 0;
#pragma unroll
        for (int c = 0; c < NUM_CLS; ++c)
            m |= (syn[c * N_BASAL + j] > 0.5f) ? (1u << c) : 0u;
        g_mask[j] = m;
    }
}

// ---------------------------------------------------------------------------
// A: bf16(image), K padded with zeros
// ---------------------------------------------------------------------------
__global__ void conv_a_kernel(const float* __restrict__ img) {
    size_t idx = (size_t)blockIdx.x * 256 + threadIdx.x;   // 4096*800
    int m = (int)(idx / K_PAD);
    int k = (int)(idx % K_PAD);
    g_A[idx] = (k < K_DIM) ? __float2bfloat16(img[(size_t)m * K_DIM + k])
                           : __float2bfloat16(0.0f);
}

// ---------------------------------------------------------------------------
// B: transpose proj -> bf16 g_B [n][K_PAD] and fp32 g_Bt [n][K_DIM]
// ---------------------------------------------------------------------------
__global__ void conv_b_kernel(const float* __restrict__ proj) {
    __shared__ float t[32][33];
    int k0 = blockIdx.x * 32, n0 = blockIdx.y * 32;
    int tx = threadIdx.x, ty = threadIdx.y;   // 32 x 8
#pragma unroll
    for (int i = 0; i < 32; i += 8) {
        int kk = k0 + ty + i;
        t[ty + i][tx] = (kk < K_DIM) ? proj[(size_t)kk * N_BASAL + n0 + tx] : 0.0f;
    }
    __syncthreads();
#pragma unroll
    for (int i = 0; i < 32; i += 8) {
        int n = n0 + ty + i;
        int k = k0 + tx;
        if (k < K_PAD) {
            float v = t[tx][ty + i];
            g_B[(size_t)n * K_PAD + k] = __float2bfloat16(v);
            if (k < K_DIM) g_Bt[(size_t)n * K_DIM + k] = v;
        }
    }
}

// ---------------------------------------------------------------------------
// mma.sync bf16 GEMM: g_act[M,N](fp16) = g_A[M,Kp] * g_B[N,Kp]^T (fp32 accum)
// ---------------------------------------------------------------------------
__global__ __launch_bounds__(256, 2)
void gemm_mma_kernel() {
    extern __shared__ char smem[];
    const uint32_t sb = smem_u32(smem);
    const int tid = threadIdx.x;
    const int lane = tid & 31;
    const int wid = tid >> 5;
    const int warpM = wid >> 2;
    const int warpN = wid & 3;
    const int m0 = blockIdx.y * BM;
    const int n0 = blockIdx.x * BN;

    const char* Abase = (const char*)g_A + (size_t)m0 * (K_PAD * 2);
    const char* Bbase = (const char*)g_B + (size_t)n0 * (K_PAD * 2);

    const int ar = tid >> 2;
    const int ac = tid & 3;

    auto load_stage = [&](int c, int s) {
        const uint32_t st = sb + s * STAGE_BYTES;
        const size_t koff = (size_t)c * (BK * 2);
        cp_async16(st + ar * ROW_BYTES + ac * 16,
                   Abase + (size_t)ar * (K_PAD * 2) + koff + ac * 16);
        cp_async16(st + (ar + 64) * ROW_BYTES + ac * 16,
                   Abase + (size_t)(ar + 64) * (K_PAD * 2) + koff + ac * 16);
        const uint32_t stB = st + A_STAGE_BYTES;
        cp_async16(stB + ar * ROW_BYTES + ac * 16,
                   Bbase + (size_t)ar * (K_PAD * 2) + koff + ac * 16);
        cp_async16(stB + (ar + 64) * ROW_BYTES + ac * 16,
                   Bbase + (size_t)(ar + 64) * (K_PAD * 2) + koff + ac * 16);
        cp_commit();
    };

    float acc[4][4][4];
#pragma unroll
    for (int i = 0; i < 4; ++i)
#pragma unroll
        for (int j = 0; j < 4; ++j)
#pragma unroll
            for (int q = 0; q < 4; ++q) acc[i][j][q] = 0.0f;

    const int lrow = lane & 15;
    const int lcol16 = (lane >> 4) << 4;

    load_stage(0, 0);
    load_stage(1, 1);
    load_stage(2, 2);

    for (int c = 0; c < NCHUNK; ++c) {
        const int s = c & 3;
        cp_wait<2>();
        __syncthreads();
        if (c + 3 < NCHUNK) load_stage(c + 3, (c + 3) & 3);
        else cp_commit();   // empty group keeps wait accounting safe

        const uint32_t stA = sb + s * STAGE_BYTES;
        const uint32_t stB = stA + A_STAGE_BYTES;
#pragma unroll
        for (int ks = 0; ks < 2; ++ks) {
            const int kbyte = ks * 32 + lcol16;
            uint32_t af[4][4];
#pragma unroll
            for (int mt = 0; mt < 4; ++mt)
                ldm_x4(af[mt], stA + (warpM * 64 + mt * 16 + lrow) * ROW_BYTES + kbyte);
            uint32_t bf[2][4];
#pragma unroll
            for (int nt = 0; nt < 2; ++nt)
                ldm_x4(bf[nt], stB + (warpN * 32 + nt * 16 + lrow) * ROW_BYTES + kbyte);
#pragma unroll
            for (int mt = 0; mt < 4; ++mt) {
#pragma unroll
                for (int n8 = 0; n8 < 4; ++n8) {
                    const int nt = n8 >> 1, hi = n8 & 1;
                    mma_bf16(acc[mt][n8], af[mt], bf[nt][hi], bf[nt][hi + 2]);
                }
            }
        }
    }

    // epilogue: fp32 -> fp16 pairs
    const int grp = lane >> 2;
    const int tj  = lane & 3;
#pragma unroll
    for (int mt = 0; mt < 4; ++mt) {
#pragma unroll
        for (int n8 = 0; n8 < 4; ++n8) {
            const int row = m0 + warpM * 64 + mt * 16 + grp;
            const int col = n0 + warpN * 32 + n8 * 8 + tj * 2;
            __half2* p0 = (__half2*)(g_act + (size_t)row * N_BASAL + col);
            __half2* p1 = (__half2*)(g_act + (size_t)(row + 8) * N_BASAL + col);
            *p0 = __floats2half2_rn(acc[mt][n8][0], acc[mt][n8][1]);
            *p1 = __floats2half2_rn(acc[mt][n8][2], acc[mt][n8][3]);
        }
    }
}

// ---------------------------------------------------------------------------
// select + overlap: 1 linear-bin hist pass + 1 classify pass + exact fp32
// rescore of in-window candidates + exact rank. One block (256 thr) per row.
// ---------------------------------------------------------------------------
__global__ __launch_bounds__(256)
void select_overlap_kernel(const float* __restrict__ img, float* __restrict__ out) {
    const int row = blockIdx.x;
    const uint4* a16 = (const uint4*)(g_act + (size_t)row * N_BASAL);  // 8 halves each
    const int tid = threadIdx.x;
    const int lane = tid & 31;
    const int wid = tid >> 5;

    __shared__ unsigned int hist[HBINS];
    __shared__ float4 s_img[K_DIM / 4];
    __shared__ int s_bin;
    __shared__ int ov[NUM_CLS];
    __shared__ int s_ncand, s_nsure;
    __shared__ int   cand_idx[MAXC];
    __shared__ float cand_val[MAXC];

    const float4* img4 = (const float4*)(img + (size_t)row * K_DIM);
    for (int k = tid; k < K_DIM / 4; k += 256) s_img[k] = img4[k];

    if (tid == 0) { s_ncand = 0; s_nsure = 0; s_bin = 0; }
    if (tid < NUM_CLS) ov[tid] = 0;
    for (int i = tid; i < HBINS; i += 256) hist[i] = 0;
    __syncthreads();

    // ---- pass 1: linear histogram (low conflict for ~Gaussian data) ----
    for (int j = tid; j < N_BASAL / 8; j += 256) {
        uint4 u = a16[j];
        const unsigned int uu[4] = {u.x, u.y, u.z, u.w};
#pragma unroll
        for (int q = 0; q < 4; ++q) {
            float2 v = __half22float2(*(const __half2*)&uu[q]);
            int b0 = (int)((v.x - HLO) * HSCALE);
            int b1 = (int)((v.y - HLO) * HSCALE);
            b0 = min(max(b0, 0), HBINS - 1);
            b1 = min(max(b1, 0), HBINS - 1);
            atomicAdd(&hist[b0], 1u);
            atomicAdd(&hist[b1], 1u);
        }
    }
    __syncthreads();

    // ---- warp 0: find bin containing the NUM_ACT-th largest ----
    if (wid == 0) {
        unsigned int sum = 0;
        for (int i = 0; i < HBINS / 32; ++i)
            sum += hist[HBINS - 1 - lane * (HBINS / 32) - i];
        unsigned int pre = sum;
#pragma unroll
        for (int o = 1; o < 32; o <<= 1) {
            unsigned int t = __shfl_up_sync(0xFFFFFFFFu, pre, o);
            if (lane >= o) pre += t;
        }
        const unsigned int excl = pre - sum;
        if (excl < NUM_ACT && pre >= NUM_ACT) {
            unsigned int before = excl;
            for (int i = 0; i < HBINS / 32; ++i) {
                int b = HBINS - 1 - lane * (HBINS / 32) - i;
                unsigned int cc = hist[b];
                if (before + cc >= NUM_ACT) { s_bin = b; break; }
                before += cc;
            }
        }
    }
    __syncthreads();

    const float tau_lo = HLO + (float)s_bin * HWIDTH;
    const float hicut  = tau_lo + HWIDTH + 2.0f * DELTA;
    const float locut  = tau_lo - 2.0f * DELTA;

    // ---- pass 2: classify ----
    int cnt[NUM_CLS];
#pragma unroll
    for (int c = 0; c < NUM_CLS; ++c) cnt[c] = 0;
    int nsure = 0;

    for (int j = tid; j < N_BASAL / 8; j += 256) {
        uint4 u = a16[j];
        const unsigned int uu[4] = {u.x, u.y, u.z, u.w};
#pragma unroll
        for (int q = 0; q < 4; ++q) {
            float2 v = __half22float2(*(const __half2*)&uu[q]);
            const float vv[2] = {v.x, v.y};
#pragma unroll
            for (int h = 0; h < 2; ++h) {
                float x = vv[h];
                if (x > hicut) {
                    unsigned int m = g_mask[j * 8 + q * 2 + h];
#pragma unroll
                    for (int c = 0; c < NUM_CLS; ++c) cnt[c] += (m >> c) & 1u;
                    ++nsure;
                } else if (x >= locut) {
                    int p = atomicAdd(&s_ncand, 1);
                    if (p < MAXC) cand_idx[p] = j * 8 + q * 2 + h;
                }
            }
        }
    }
    atomicAdd(&s_nsure, nsure);
    __syncthreads();

    const int C = (s_ncand < MAXC) ? s_ncand : MAXC;
    const int k_remain = NUM_ACT - s_nsure;

    // ---- exact fp32 rescore: one warp per candidate ----
    for (int c = wid; c < C; c += 8) {
        const float4* brow = (const float4*)(g_Bt + (size_t)cand_idx[c] * K_DIM);
        float s = 0.0f;
        for (int k = lane; k < K_DIM / 4; k += 32) {
            float4 b = brow[k];
            float4 im = s_img[k];
            s = fmaf(im.x, b.x, s);
            s = fmaf(im.y, b.y, s);
            s = fmaf(im.z, b.z, s);
            s = fmaf(im.w, b.w, s);
        }
#pragma unroll
        for (int o = 16; o > 0; o >>= 1)
            s += __shfl_xor_sync(0xFFFFFFFFu, s, o);
        if (lane == 0) cand_val[c] = s;
    }
    __syncthreads();

    // ---- exact rank among candidates (value desc, index asc) ----
    for (int c = tid; c < C; c += 256) {
        const float vc = cand_val[c];
        const int ic = cand_idx[c];
        int rank = 0;
        for (int d = 0; d < C; ++d) {
            float vd = cand_val[d];
            rank += (vd > vc || (vd == vc && cand_idx[d] < ic)) ? 1 : 0;
        }
        if (rank < k_remain) {
            unsigned int m = g_mask[ic];
#pragma unroll
            for (int cc = 0; cc < NUM_CLS; ++cc) cnt[cc] += (m >> cc) & 1u;
        }
    }

#pragma unroll
    for (int c = 0; c < NUM_CLS; ++c)
        if (cnt[c]) atomicAdd(&ov[c], cnt[c]);
    __syncthreads();

    if (tid < NUM_CLS)
        out[row * NUM_CLS + tid] = (float)ov[tid];
}

// ---------------------------------------------------------------------------
// Launch
// ---------------------------------------------------------------------------
extern "C" void kernel_launch(void* const* d_in, const int* in_sizes, int n_in,
                              void* d_out, int out_size) {
    const float* image = (const float*)d_in[0];   // [4096, 784]
    const float* proj  = (const float*)d_in[1];   // [784, 16384]
    const float* syn   = (const float*)d_in[2];   // [10, 16384]
    float* out = (float*)d_out;                   // [4096, 10]

    cudaFuncSetAttribute(gemm_mma_kernel, cudaFuncAttributeMaxDynamicSharedMemorySize, SMEM_TOTAL);

    pack_syn_kernel<<<(N_BASAL + 255) / 256, 256>>>(syn);
    conv_a_kernel<<<(int)(((size_t)M_ROWS * K_PAD) / 256), 256>>>(image);
    {
        dim3 grid(K_PAD / 32, N_BASAL / 32);      // 25 x 512
        conv_b_kernel<<<grid, dim3(32, 8)>>>(proj);
    }
    {
        dim3 grid(N_BASAL / BN, M_ROWS / BM);     // 128 x 32
        gemm_mma_kernel<<<grid, 256, SMEM_TOTAL>>>();
    }
    select_overlap_kernel<<<M_ROWS, 256>>>(image, out);
}